// round 8
// baseline (speedup 1.0000x reference)
#include <cuda_runtime.h>
#include <cstdint>
#include <cstddef>

// Problem constants (fixed shapes)
#define HDIM   2048
#define IDIM   1024
#define TTOK   4096   // B*S
#define NEXP   8      // routed experts
#define NTOT   12     // routed + zero
#define TOPK   2
#define RSCALE 1.5f

// ---------------- device scratch (no allocations allowed) ----------------
__device__ int   g_cnt[NEXP];
__device__ int   g_tok[NEXP * TTOK];
__device__ float g_wgt[NEXP * TTOK];
__device__ float g_act[(size_t)NEXP * TTOK * IDIM];   // 128 MB fp32 scratch

// ---------------- packed fp32x2 helpers (Blackwell dual fp32 pipe) -------
static __device__ __forceinline__ unsigned long long pk2(float lo, float hi) {
    unsigned long long r;
    asm("mov.b64 %0, {%1, %2};" : "=l"(r) : "f"(lo), "f"(hi));
    return r;
}
static __device__ __forceinline__ unsigned long long fma2(
    unsigned long long a, unsigned long long b, unsigned long long c) {
    unsigned long long d;
    asm("fma.rn.f32x2 %0, %1, %2, %3;" : "=l"(d) : "l"(a), "l"(b), "l"(c));
    return d;
}
static __device__ __forceinline__ float2 upk(unsigned long long v) {
    float2 f;
    asm("mov.b64 {%0, %1}, %2;" : "=f"(f.x), "=f"(f.y) : "l"(v));
    return f;
}

// ---------------- kernel 0: zero the per-expert counters -----------------
__global__ void k_zero_cnt() {
    if (threadIdx.x < NEXP) g_cnt[threadIdx.x] = 0;
}

// ---------------- kernel 1: router + identity-expert output init ---------
// 1 warp per token. Computes 12 logits, softmax, biased top-2,
// scatters (token, weight) into per-expert lists, and writes
// out[t] = x[t] * (sum of selected zero-expert weights).
__global__ void __launch_bounds__(128) k_router(
    const float* __restrict__ x,
    const float* __restrict__ cw,
    const float* __restrict__ bias,
    float* __restrict__ out)
{
    const int warp = threadIdx.x >> 5;
    const int lane = threadIdx.x & 31;
    const int t = blockIdx.x * 4 + warp;

    const float* xr = x + (size_t)t * HDIM;

    float acc[NTOT];
#pragma unroll
    for (int e = 0; e < NTOT; e++) acc[e] = 0.f;

    for (int h = lane; h < HDIM; h += 32) {
        const float xv = xr[h];
#pragma unroll
        for (int e = 0; e < NTOT; e++)
            acc[e] = fmaf(xv, cw[e * HDIM + h], acc[e]);
    }
#pragma unroll
    for (int e = 0; e < NTOT; e++) {
#pragma unroll
        for (int o = 16; o > 0; o >>= 1)
            acc[e] += __shfl_xor_sync(0xFFFFFFFFu, acc[e], o);
    }

    float wid = 0.f;
    if (lane == 0) {
        // stable softmax over 12
        float mx = acc[0];
#pragma unroll
        for (int e = 1; e < NTOT; e++) mx = fmaxf(mx, acc[e]);
        float p[NTOT], den = 0.f;
#pragma unroll
        for (int e = 0; e < NTOT; e++) { p[e] = __expf(acc[e] - mx); den += p[e]; }
        const float inv = 1.0f / den;

        float bv[NTOT];
#pragma unroll
        for (int e = 0; e < NTOT; e++) bv[e] = p[e] * inv + bias[e];

        // top-2, ties -> lower index (strict > keeps first max, matching jax)
        int i0 = 0; float b0 = bv[0];
#pragma unroll
        for (int e = 1; e < NTOT; e++) if (bv[e] > b0) { b0 = bv[e]; i0 = e; }
        int i1 = -1; float b1 = -3.4e38f;
#pragma unroll
        for (int e = 0; e < NTOT; e++)
            if (e != i0 && bv[e] > b1) { b1 = bv[e]; i1 = e; }

        const int   sel[2] = { i0, i1 };
#pragma unroll
        for (int k = 0; k < 2; k++) {
            const int   ie = sel[k];
            const float w  = p[ie] * inv * RSCALE;
            if (ie < NEXP) {
                const int s = atomicAdd(&g_cnt[ie], 1);
                g_tok[ie * TTOK + s] = t;
                g_wgt[ie * TTOK + s] = w;
            } else {
                wid += w;
            }
        }
    }
    wid = __shfl_sync(0xFFFFFFFFu, wid, 0);

    float* orow = out + (size_t)t * HDIM;
    for (int h = lane; h < HDIM; h += 32) orow[h] = xr[h] * wid;
}

// ---------------- kernel 2: gathered gate+up GEMM + silu -----------------
// Tile: 128 tokens x 64 inter-cols, K=2048, BK=16, 256 thr, 8m x 4n x {g,u}.
// act[e][slot][i] = silu(x@gate^T) * (x@up^T)
__global__ void __launch_bounds__(256) k_gemm1(
    const float* __restrict__ x,
    const float* __restrict__ gate,
    const float* __restrict__ up)
{
    __shared__ float As[16 * 132];
    __shared__ float Bg[16 * 68];
    __shared__ float Bu[16 * 68];
    __shared__ int   tok_s[128];

    const int e   = blockIdx.z;
    const int cnt = g_cnt[e];
    const int r0  = blockIdx.y * 128;
    if (r0 >= cnt) return;
    const int n0  = blockIdx.x * 64;
    const int tid = threadIdx.x;

    if (tid < 128) {
        int r = r0 + tid;
        tok_s[tid] = g_tok[e * TTOK + (r < cnt ? r : cnt - 1)];
    }
    __syncthreads();

    const int rA = tid >> 2;          // 0..63
    const int q4 = (tid & 3) * 4;     // 0,4,8,12

    const float* pa0 = x + (size_t)tok_s[rA]      * HDIM + q4;
    const float* pa1 = x + (size_t)tok_s[rA + 64] * HDIM + q4;
    const float* pg  = gate + ((size_t)e * IDIM + n0 + rA) * HDIM + q4;
    const float* pu  = up   + ((size_t)e * IDIM + n0 + rA) * HDIM + q4;

    const int ty = tid >> 4, tx = tid & 15;
    const int m_off = ty * 8, n_off = tx * 4;

    unsigned long long cg[8][2], cu[8][2];
#pragma unroll
    for (int m = 0; m < 8; m++) { cg[m][0]=0ULL; cg[m][1]=0ULL; cu[m][0]=0ULL; cu[m][1]=0ULL; }

    for (int kk = 0; kk < HDIM; kk += 16) {
        const float4 a0 = *(const float4*)(pa0 + kk);
        const float4 a1 = *(const float4*)(pa1 + kk);
        const float4 g0 = *(const float4*)(pg  + kk);
        const float4 u0 = *(const float4*)(pu  + kk);
        __syncthreads();
        As[(q4+0)*132 + rA]      = a0.x;
        As[(q4+1)*132 + rA]      = a0.y;
        As[(q4+2)*132 + rA]      = a0.z;
        As[(q4+3)*132 + rA]      = a0.w;
        As[(q4+0)*132 + rA + 64] = a1.x;
        As[(q4+1)*132 + rA + 64] = a1.y;
        As[(q4+2)*132 + rA + 64] = a1.z;
        As[(q4+3)*132 + rA + 64] = a1.w;
        Bg[(q4+0)*68 + rA] = g0.x;
        Bg[(q4+1)*68 + rA] = g0.y;
        Bg[(q4+2)*68 + rA] = g0.z;
        Bg[(q4+3)*68 + rA] = g0.w;
        Bu[(q4+0)*68 + rA] = u0.x;
        Bu[(q4+1)*68 + rA] = u0.y;
        Bu[(q4+2)*68 + rA] = u0.z;
        Bu[(q4+3)*68 + rA] = u0.w;
        __syncthreads();

#pragma unroll 8
        for (int k = 0; k < 16; k++) {
            const float4 av0 = *(const float4*)&As[k*132 + m_off];
            const float4 av1 = *(const float4*)&As[k*132 + m_off + 4];
            const float4 bg4 = *(const float4*)&Bg[k*68 + n_off];
            const float4 bu4 = *(const float4*)&Bu[k*68 + n_off];
            const unsigned long long bgp0 = pk2(bg4.x, bg4.y);
            const unsigned long long bgp1 = pk2(bg4.z, bg4.w);
            const unsigned long long bup0 = pk2(bu4.x, bu4.y);
            const unsigned long long bup1 = pk2(bu4.z, bu4.w);
            const float am[8] = {av0.x, av0.y, av0.z, av0.w, av1.x, av1.y, av1.z, av1.w};
#pragma unroll
            for (int m = 0; m < 8; m++) {
                const unsigned long long aa = pk2(am[m], am[m]);
                cg[m][0] = fma2(aa, bgp0, cg[m][0]);
                cg[m][1] = fma2(aa, bgp1, cg[m][1]);
                cu[m][0] = fma2(aa, bup0, cu[m][0]);
                cu[m][1] = fma2(aa, bup1, cu[m][1]);
            }
        }
    }

#pragma unroll
    for (int mi = 0; mi < 8; mi++) {
        const int slot = r0 + m_off + mi;
        if (slot < cnt) {
            const float2 gA = upk(cg[mi][0]), gB = upk(cg[mi][1]);
            const float2 uA = upk(cu[mi][0]), uB = upk(cu[mi][1]);
            float4 o;
            o.x = (gA.x / (1.0f + __expf(-gA.x))) * uA.x;
            o.y = (gA.y / (1.0f + __expf(-gA.y))) * uA.y;
            o.z = (gB.x / (1.0f + __expf(-gB.x))) * uB.x;
            o.w = (gB.y / (1.0f + __expf(-gB.y))) * uB.y;
            *(float4*)&g_act[((size_t)e * TTOK + slot) * IDIM + n0 + n_off] = o;
        }
    }
}

// ---------------- kernel 3: down GEMM + weighted scatter-add -------------
// Tile: 128 tokens x 128 h-cols, K=1024, BK=16, 256 thr, 8x8.
__global__ void __launch_bounds__(256) k_gemm2(
    const float* __restrict__ down,
    float* __restrict__ out)
{
    __shared__ float As[16 * 132];
    __shared__ float Bs[16 * 132];
    __shared__ int   tok_s[128];
    __shared__ float w_s[128];

    const int e   = blockIdx.z;
    const int cnt = g_cnt[e];
    const int r0  = blockIdx.y * 128;
    if (r0 >= cnt) return;
    const int n0  = blockIdx.x * 128;
    const int tid = threadIdx.x;

    if (tid < 128) {
        int r = r0 + tid;
        int rc = (r < cnt ? r : cnt - 1);
        tok_s[tid] = g_tok[e * TTOK + rc];
        w_s[tid]   = g_wgt[e * TTOK + rc];
    }
    __syncthreads();

    const int rA = tid >> 2;
    const int q4 = (tid & 3) * 4;

    const int s0 = r0 + rA;
    const int s1 = r0 + rA + 64;
    const int s0c = (s0 < cnt ? s0 : cnt - 1);
    const int s1c = (s1 < cnt ? s1 : cnt - 1);

    const float* pa0 = g_act + ((size_t)e * TTOK + s0c) * IDIM + q4;
    const float* pa1 = g_act + ((size_t)e * TTOK + s1c) * IDIM + q4;
    const float* pb0 = down + (size_t)e * HDIM * IDIM + (size_t)(n0 + rA)      * IDIM + q4;
    const float* pb1 = down + (size_t)e * HDIM * IDIM + (size_t)(n0 + rA + 64) * IDIM + q4;

    const int ty = tid >> 4, tx = tid & 15;
    const int m_off = ty * 8, n_off = tx * 8;

    unsigned long long c[8][4];
#pragma unroll
    for (int m = 0; m < 8; m++) { c[m][0]=0ULL; c[m][1]=0ULL; c[m][2]=0ULL; c[m][3]=0ULL; }

    for (int kk = 0; kk < IDIM; kk += 16) {
        const float4 a0 = *(const float4*)(pa0 + kk);
        const float4 a1 = *(const float4*)(pa1 + kk);
        const float4 b0 = *(const float4*)(pb0 + kk);
        const float4 b1 = *(const float4*)(pb1 + kk);
        __syncthreads();
        As[(q4+0)*132 + rA]      = a0.x;
        As[(q4+1)*132 + rA]      = a0.y;
        As[(q4+2)*132 + rA]      = a0.z;
        As[(q4+3)*132 + rA]      = a0.w;
        As[(q4+0)*132 + rA + 64] = a1.x;
        As[(q4+1)*132 + rA + 64] = a1.y;
        As[(q4+2)*132 + rA + 64] = a1.z;
        As[(q4+3)*132 + rA + 64] = a1.w;
        Bs[(q4+0)*132 + rA]      = b0.x;
        Bs[(q4+1)*132 + rA]      = b0.y;
        Bs[(q4+2)*132 + rA]      = b0.z;
        Bs[(q4+3)*132 + rA]      = b0.w;
        Bs[(q4+0)*132 + rA + 64] = b1.x;
        Bs[(q4+1)*132 + rA + 64] = b1.y;
        Bs[(q4+2)*132 + rA + 64] = b1.z;
        Bs[(q4+3)*132 + rA + 64] = b1.w;
        __syncthreads();

#pragma unroll 8
        for (int k = 0; k < 16; k++) {
            const float4 av0 = *(const float4*)&As[k*132 + m_off];
            const float4 av1 = *(const float4*)&As[k*132 + m_off + 4];
            const float4 bv0 = *(const float4*)&Bs[k*132 + n_off];
            const float4 bv1 = *(const float4*)&Bs[k*132 + n_off + 4];
            const unsigned long long bp0 = pk2(bv0.x, bv0.y);
            const unsigned long long bp1 = pk2(bv0.z, bv0.w);
            const unsigned long long bp2 = pk2(bv1.x, bv1.y);
            const unsigned long long bp3 = pk2(bv1.z, bv1.w);
            const float am[8] = {av0.x, av0.y, av0.z, av0.w, av1.x, av1.y, av1.z, av1.w};
#pragma unroll
            for (int m = 0; m < 8; m++) {
                const unsigned long long aa = pk2(am[m], am[m]);
                c[m][0] = fma2(aa, bp0, c[m][0]);
                c[m][1] = fma2(aa, bp1, c[m][1]);
                c[m][2] = fma2(aa, bp2, c[m][2]);
                c[m][3] = fma2(aa, bp3, c[m][3]);
            }
        }
    }

#pragma unroll
    for (int mi = 0; mi < 8; mi++) {
        const int slot = r0 + m_off + mi;
        if (slot < cnt) {
            const float w = w_s[m_off + mi];
            const int   t = tok_s[m_off + mi];
            float* orow = out + (size_t)t * HDIM + n0 + n_off;
#pragma unroll
            for (int p = 0; p < 4; p++) {
                const float2 v = upk(c[mi][p]);
                atomicAdd(&orow[2*p + 0], w * v.x);
                atomicAdd(&orow[2*p + 1], w * v.y);
            }
        }
    }
}

// ---------------- launch ---------------------------------------------------
extern "C" void kernel_launch(void* const* d_in, const int* in_sizes, int n_in,
                              void* d_out, int out_size)
{
    (void)in_sizes; (void)n_in; (void)out_size;
    const float* x    = (const float*)d_in[0];   // [2,2048,2048]
    const float* cw   = (const float*)d_in[1];   // [12,2048]
    const float* bias = (const float*)d_in[2];   // [12]
    const float* gw   = (const float*)d_in[3];   // [8,1024,2048]
    const float* uw   = (const float*)d_in[4];   // [8,1024,2048]
    const float* dw   = (const float*)d_in[5];   // [8,2048,1024]
    float* out = (float*)d_out;                  // [2,2048,2048]

    k_zero_cnt<<<1, 32>>>();
    k_router<<<TTOK / 4, 128>>>(x, cw, bias, out);
    k_gemm1<<<dim3(IDIM / 64, TTOK / 128, NEXP), 256>>>(x, gw, uw);
    k_gemm2<<<dim3(HDIM / 128, TTOK / 128, NEXP), 256>>>(dw, out);
}

// round 11
// speedup vs baseline: 2.0721x; 2.0721x over previous
#include <cuda_runtime.h>
#include <cstdint>
#include <cstddef>

// Problem constants (fixed shapes)
#define HDIM   2048
#define IDIM   1024
#define TTOK   4096   // B*S
#define NEXP   8      // routed experts
#define NTOT   12     // routed + zero
#define RSCALE 1.5f

// ---------------- device scratch (no allocations allowed) ----------------
__device__ int   g_cnt[NEXP];
__device__ int   g_tok[NEXP * TTOK];
__device__ float g_wgt[NEXP * TTOK];
__device__ float g_act[(size_t)NEXP * TTOK * IDIM];   // 128 MB fp32 scratch

// ---------------- helpers -------------------------------------------------
static __device__ __forceinline__ uint32_t to_tf32(float f) {
    uint32_t u;
    asm("cvt.rna.tf32.f32 %0, %1;" : "=r"(u) : "f"(f));
    return u;
}
// d += a(16x8 tf32, row) * b(8x8 tf32, col)
static __device__ __forceinline__ void mma_tf32(float* d, const uint32_t* a,
                                                const uint32_t* b) {
    asm volatile(
        "mma.sync.aligned.m16n8k8.row.col.f32.tf32.tf32.f32 "
        "{%0,%1,%2,%3}, {%4,%5,%6,%7}, {%8,%9}, {%0,%1,%2,%3};"
        : "+f"(d[0]), "+f"(d[1]), "+f"(d[2]), "+f"(d[3])
        : "r"(a[0]), "r"(a[1]), "r"(a[2]), "r"(a[3]), "r"(b[0]), "r"(b[1]));
}

// ---------------- kernel 0: zero the per-expert counters -----------------
__global__ void k_zero_cnt() {
    if (threadIdx.x < NEXP) g_cnt[threadIdx.x] = 0;
}

// ---------------- kernel 1: router + identity-expert output init ---------
__global__ void __launch_bounds__(128) k_router(
    const float* __restrict__ x,
    const float* __restrict__ cw,
    const float* __restrict__ bias,
    float* __restrict__ out)
{
    const int warp = threadIdx.x >> 5;
    const int lane = threadIdx.x & 31;
    const int t = blockIdx.x * 4 + warp;

    const float* xr = x + (size_t)t * HDIM;

    float acc[NTOT];
#pragma unroll
    for (int e = 0; e < NTOT; e++) acc[e] = 0.f;

    for (int h = lane; h < HDIM; h += 32) {
        const float xv = xr[h];
#pragma unroll
        for (int e = 0; e < NTOT; e++)
            acc[e] = fmaf(xv, cw[e * HDIM + h], acc[e]);
    }
#pragma unroll
    for (int e = 0; e < NTOT; e++) {
#pragma unroll
        for (int o = 16; o > 0; o >>= 1)
            acc[e] += __shfl_xor_sync(0xFFFFFFFFu, acc[e], o);
    }

    float wid = 0.f;
    if (lane == 0) {
        float mx = acc[0];
#pragma unroll
        for (int e = 1; e < NTOT; e++) mx = fmaxf(mx, acc[e]);
        float p[NTOT], den = 0.f;
#pragma unroll
        for (int e = 0; e < NTOT; e++) { p[e] = __expf(acc[e] - mx); den += p[e]; }
        const float inv = 1.0f / den;

        float bv[NTOT];
#pragma unroll
        for (int e = 0; e < NTOT; e++) bv[e] = p[e] * inv + bias[e];

        int i0 = 0; float b0 = bv[0];
#pragma unroll
        for (int e = 1; e < NTOT; e++) if (bv[e] > b0) { b0 = bv[e]; i0 = e; }
        int i1 = -1; float b1 = -3.4e38f;
#pragma unroll
        for (int e = 0; e < NTOT; e++)
            if (e != i0 && bv[e] > b1) { b1 = bv[e]; i1 = e; }

        const int sel[2] = { i0, i1 };
#pragma unroll
        for (int k = 0; k < 2; k++) {
            const int   ie = sel[k];
            const float w  = p[ie] * inv * RSCALE;
            if (ie < NEXP) {
                const int s = atomicAdd(&g_cnt[ie], 1);
                g_tok[ie * TTOK + s] = t;
                g_wgt[ie * TTOK + s] = w;
            } else {
                wid += w;
            }
        }
    }
    wid = __shfl_sync(0xFFFFFFFFu, wid, 0);

    float* orow = out + (size_t)t * HDIM;
    for (int h = lane; h < HDIM; h += 32) orow[h] = xr[h] * wid;
}

// ================= kernel 2: gathered gate+up tf32 MMA + silu ============
// CTA tile: 128 tokens x 64 inter cols (for both gate & up), BK=16.
// 8 warps: warp_m = wid>>2 (m base 64*warp_m), warp_n = wid&3 (16 cols).
// Per warp: 4 m-tiles x 2 n-tiles x {g,u} = 16 mma / k8-step.
#define LDA 136
#define LDB 72
__global__ void __launch_bounds__(256) k_gemm1(
    const float* __restrict__ x,
    const float* __restrict__ gate,
    const float* __restrict__ up)
{
    __shared__ uint32_t As[16 * LDA];
    __shared__ uint32_t Bg[16 * LDB];
    __shared__ uint32_t Bu[16 * LDB];
    __shared__ int tok_s[128];

    const int e   = blockIdx.z;
    const int cnt = g_cnt[e];
    const int r0  = blockIdx.y * 128;
    if (r0 >= cnt) return;
    const int n0  = blockIdx.x * 64;
    const int tid = threadIdx.x;

    if (tid < 128) {
        int r = r0 + tid;
        tok_s[tid] = g_tok[e * TTOK + (r < cnt ? r : cnt - 1)];
    }
    __syncthreads();

    const int rA = tid >> 2;          // 0..63
    const int q4 = (tid & 3) * 4;     // k offset 0,4,8,12

    const float* pa0 = x + (size_t)tok_s[rA]      * HDIM + q4;
    const float* pa1 = x + (size_t)tok_s[rA + 64] * HDIM + q4;
    const float* pg  = gate + ((size_t)e * IDIM + n0 + rA) * HDIM + q4;
    const float* pu  = up   + ((size_t)e * IDIM + n0 + rA) * HDIM + q4;

    const int lane = tid & 31;
    const int wid  = tid >> 5;
    const int gid  = lane >> 2;
    const int tg   = lane & 3;
    const int wm   = (wid >> 2) * 64;
    const int wn   = (wid & 3) * 16;

    float ag[4][2][4], au[4][2][4];
#pragma unroll
    for (int m = 0; m < 4; m++)
#pragma unroll
        for (int n = 0; n < 2; n++)
#pragma unroll
            for (int q = 0; q < 4; q++) { ag[m][n][q] = 0.f; au[m][n][q] = 0.f; }

    for (int kk = 0; kk < HDIM; kk += 16) {
        const float4 a0 = *(const float4*)(pa0 + kk);
        const float4 a1 = *(const float4*)(pa1 + kk);
        const float4 g0 = *(const float4*)(pg  + kk);
        const float4 u0 = *(const float4*)(pu  + kk);
        __syncthreads();
        As[(q4+0)*LDA + rA]      = to_tf32(a0.x);
        As[(q4+1)*LDA + rA]      = to_tf32(a0.y);
        As[(q4+2)*LDA + rA]      = to_tf32(a0.z);
        As[(q4+3)*LDA + rA]      = to_tf32(a0.w);
        As[(q4+0)*LDA + rA + 64] = to_tf32(a1.x);
        As[(q4+1)*LDA + rA + 64] = to_tf32(a1.y);
        As[(q4+2)*LDA + rA + 64] = to_tf32(a1.z);
        As[(q4+3)*LDA + rA + 64] = to_tf32(a1.w);
        Bg[(q4+0)*LDB + rA] = to_tf32(g0.x);
        Bg[(q4+1)*LDB + rA] = to_tf32(g0.y);
        Bg[(q4+2)*LDB + rA] = to_tf32(g0.z);
        Bg[(q4+3)*LDB + rA] = to_tf32(g0.w);
        Bu[(q4+0)*LDB + rA] = to_tf32(u0.x);
        Bu[(q4+1)*LDB + rA] = to_tf32(u0.y);
        Bu[(q4+2)*LDB + rA] = to_tf32(u0.z);
        Bu[(q4+3)*LDB + rA] = to_tf32(u0.w);
        __syncthreads();

#pragma unroll
        for (int k8 = 0; k8 < 16; k8 += 8) {
            uint32_t bg[2][2], bu[2][2];
#pragma unroll
            for (int nt = 0; nt < 2; nt++) {
                const int c = wn + nt * 8 + gid;
                bg[nt][0] = Bg[(k8 + tg)     * LDB + c];
                bg[nt][1] = Bg[(k8 + tg + 4) * LDB + c];
                bu[nt][0] = Bu[(k8 + tg)     * LDB + c];
                bu[nt][1] = Bu[(k8 + tg + 4) * LDB + c];
            }
#pragma unroll
            for (int mt = 0; mt < 4; mt++) {
                const int m = wm + mt * 16 + gid;
                uint32_t a[4];
                a[0] = As[(k8 + tg)     * LDA + m];
                a[1] = As[(k8 + tg)     * LDA + m + 8];
                a[2] = As[(k8 + tg + 4) * LDA + m];
                a[3] = As[(k8 + tg + 4) * LDA + m + 8];
#pragma unroll
                for (int nt = 0; nt < 2; nt++) {
                    mma_tf32(ag[mt][nt], a, bg[nt]);
                    mma_tf32(au[mt][nt], a, bu[nt]);
                }
            }
        }
    }

    // epilogue: silu(g)*u -> g_act
#pragma unroll
    for (int mt = 0; mt < 4; mt++) {
        const int sA = r0 + wm + mt * 16 + gid;
        const int sB = sA + 8;
#pragma unroll
        for (int nt = 0; nt < 2; nt++) {
            const int c = n0 + wn + nt * 8 + tg * 2;
            if (sA < cnt) {
                float gv0 = ag[mt][nt][0], gv1 = ag[mt][nt][1];
                float uv0 = au[mt][nt][0], uv1 = au[mt][nt][1];
                float2 o;
                o.x = gv0 / (1.f + __expf(-gv0)) * uv0;
                o.y = gv1 / (1.f + __expf(-gv1)) * uv1;
                *(float2*)&g_act[((size_t)e * TTOK + sA) * IDIM + c] = o;
            }
            if (sB < cnt) {
                float gv0 = ag[mt][nt][2], gv1 = ag[mt][nt][3];
                float uv0 = au[mt][nt][2], uv1 = au[mt][nt][3];
                float2 o;
                o.x = gv0 / (1.f + __expf(-gv0)) * uv0;
                o.y = gv1 / (1.f + __expf(-gv1)) * uv1;
                *(float2*)&g_act[((size_t)e * TTOK + sB) * IDIM + c] = o;
            }
        }
    }
}

// ================= kernel 3: down tf32 MMA + weighted scatter ============
// CTA tile: 128 slots x 128 h-cols, BK=16.
// 8 warps: warp_m = wid>>2 (64 rows), warp_n = wid&3 (32 cols).
// Per warp: 4 m-tiles x 4 n-tiles = 16 mma / k8-step.
__global__ void __launch_bounds__(256) k_gemm2(
    const float* __restrict__ down,
    float* __restrict__ out)
{
    __shared__ uint32_t As[16 * LDA];
    __shared__ uint32_t Bs[16 * LDA];
    __shared__ int   tok_s[128];
    __shared__ float w_s[128];

    const int e   = blockIdx.z;
    const int cnt = g_cnt[e];
    const int r0  = blockIdx.y * 128;
    if (r0 >= cnt) return;
    const int n0  = blockIdx.x * 128;
    const int tid = threadIdx.x;

    if (tid < 128) {
        int r = r0 + tid;
        int rc = (r < cnt ? r : cnt - 1);
        tok_s[tid] = g_tok[e * TTOK + rc];
        w_s[tid]   = g_wgt[e * TTOK + rc];
    }
    __syncthreads();

    const int rA = tid >> 2;
    const int q4 = (tid & 3) * 4;

    const int s0 = r0 + rA;
    const int s1 = r0 + rA + 64;
    const int s0c = (s0 < cnt ? s0 : cnt - 1);
    const int s1c = (s1 < cnt ? s1 : cnt - 1);

    const float* pa0 = g_act + ((size_t)e * TTOK + s0c) * IDIM + q4;
    const float* pa1 = g_act + ((size_t)e * TTOK + s1c) * IDIM + q4;
    const float* pb0 = down + (size_t)e * HDIM * IDIM + (size_t)(n0 + rA)      * IDIM + q4;
    const float* pb1 = down + (size_t)e * HDIM * IDIM + (size_t)(n0 + rA + 64) * IDIM + q4;

    const int lane = tid & 31;
    const int wid  = tid >> 5;
    const int gid  = lane >> 2;
    const int tg   = lane & 3;
    const int wm   = (wid >> 2) * 64;
    const int wn   = (wid & 3) * 32;

    float acc[4][4][4];
#pragma unroll
    for (int m = 0; m < 4; m++)
#pragma unroll
        for (int n = 0; n < 4; n++)
#pragma unroll
            for (int q = 0; q < 4; q++) acc[m][n][q] = 0.f;

    for (int kk = 0; kk < IDIM; kk += 16) {
        const float4 a0 = *(const float4*)(pa0 + kk);
        const float4 a1 = *(const float4*)(pa1 + kk);
        const float4 b0 = *(const float4*)(pb0 + kk);
        const float4 b1 = *(const float4*)(pb1 + kk);
        __syncthreads();
        As[(q4+0)*LDA + rA]      = to_tf32(a0.x);
        As[(q4+1)*LDA + rA]      = to_tf32(a0.y);
        As[(q4+2)*LDA + rA]      = to_tf32(a0.z);
        As[(q4+3)*LDA + rA]      = to_tf32(a0.w);
        As[(q4+0)*LDA + rA + 64] = to_tf32(a1.x);
        As[(q4+1)*LDA + rA + 64] = to_tf32(a1.y);
        As[(q4+2)*LDA + rA + 64] = to_tf32(a1.z);
        As[(q4+3)*LDA + rA + 64] = to_tf32(a1.w);
        Bs[(q4+0)*LDA + rA]      = to_tf32(b0.x);
        Bs[(q4+1)*LDA + rA]      = to_tf32(b0.y);
        Bs[(q4+2)*LDA + rA]      = to_tf32(b0.z);
        Bs[(q4+3)*LDA + rA]      = to_tf32(b0.w);
        Bs[(q4+0)*LDA + rA + 64] = to_tf32(b1.x);
        Bs[(q4+1)*LDA + rA + 64] = to_tf32(b1.y);
        Bs[(q4+2)*LDA + rA + 64] = to_tf32(b1.z);
        Bs[(q4+3)*LDA + rA + 64] = to_tf32(b1.w);
        __syncthreads();

#pragma unroll
        for (int k8 = 0; k8 < 16; k8 += 8) {
            uint32_t b[4][2];
#pragma unroll
            for (int nt = 0; nt < 4; nt++) {
                const int c = wn + nt * 8 + gid;
                b[nt][0] = Bs[(k8 + tg)     * LDA + c];
                b[nt][1] = Bs[(k8 + tg + 4) * LDA + c];
            }
#pragma unroll
            for (int mt = 0; mt < 4; mt++) {
                const int m = wm + mt * 16 + gid;
                uint32_t a[4];
                a[0] = As[(k8 + tg)     * LDA + m];
                a[1] = As[(k8 + tg)     * LDA + m + 8];
                a[2] = As[(k8 + tg + 4) * LDA + m];
                a[3] = As[(k8 + tg + 4) * LDA + m + 8];
#pragma unroll
                for (int nt = 0; nt < 4; nt++)
                    mma_tf32(acc[mt][nt], a, b[nt]);
            }
        }
    }

    // epilogue: weighted atomic scatter to out
#pragma unroll
    for (int mt = 0; mt < 4; mt++) {
        const int rowA = wm + mt * 16 + gid;
        const int rowB = rowA + 8;
        const int sA = r0 + rowA;
        const int sB = r0 + rowB;
#pragma unroll
        for (int nt = 0; nt < 4; nt++) {
            const int c = n0 + wn + nt * 8 + tg * 2;
            if (sA < cnt) {
                const float w = w_s[rowA];
                float* orow = out + (size_t)tok_s[rowA] * HDIM + c;
                atomicAdd(orow + 0, w * acc[mt][nt][0]);
                atomicAdd(orow + 1, w * acc[mt][nt][1]);
            }
            if (sB < cnt) {
                const float w = w_s[rowB];
                float* orow = out + (size_t)tok_s[rowB] * HDIM + c;
                atomicAdd(orow + 0, w * acc[mt][nt][2]);
                atomicAdd(orow + 1, w * acc[mt][nt][3]);
            }
        }
    }
}

// ---------------- launch ---------------------------------------------------
extern "C" void kernel_launch(void* const* d_in, const int* in_sizes, int n_in,
                              void* d_out, int out_size)
{
    (void)in_sizes; (void)n_in; (void)out_size;
    const float* x    = (const float*)d_in[0];   // [2,2048,2048]
    const float* cw   = (const float*)d_in[1];   // [12,2048]
    const float* bias = (const float*)d_in[2];   // [12]
    const float* gw   = (const float*)d_in[3];   // [8,1024,2048]
    const float* uw   = (const float*)d_in[4];   // [8,1024,2048]
    const float* dw   = (const float*)d_in[5];   // [8,2048,1024]
    float* out = (float*)d_out;                  // [2,2048,2048]

    k_zero_cnt<<<1, 32>>>();
    k_router<<<TTOK / 4, 128>>>(x, cw, bias, out);
    k_gemm1<<<dim3(IDIM / 64, TTOK / 128, NEXP), 256>>>(x, gw, uw);
    k_gemm2<<<dim3(HDIM / 128, TTOK / 128, NEXP), 256>>>(dw, out);
}